// round 4
// baseline (speedup 1.0000x reference)
#include <cuda_runtime.h>
#include <cuda_bf16.h>
#include <cstddef>

// Problem constants
#define BATCH   2
#define TLEN    2048       // Tq == Tv
#define DMODEL  512
#define NHEADS  8
#define DHEAD   64

// Tiling
#define TQ      32         // queries per block
#define TK      32         // keys per tile
#define KSPLIT  8          // k-range splits per (b, q-tile)
#define KRANGE  (TLEN / KSPLIT)   // 256 keys per block -> 8 tiles of 32

// Shared layout (floats): Ksh[TK*DMODEL] | Vsh[TK*DHEAD] | Sp[2*NHEADS*TK*TQ]
#define KSH_FLOATS  (TK * DMODEL)                 // 16384 (64KB)
#define VSH_FLOATS  (TK * DHEAD)                  // 2048  (8KB)
#define SPHALF      (NHEADS * TK * TQ)            // 8192
#define SP_FLOATS   (2 * SPHALF)                  // 16384 (64KB)
#define SMEM_FLOATS (KSH_FLOATS + VSH_FLOATS + SP_FLOATS)
#define SMEM_BYTES  (SMEM_FLOATS * 4)             // 139264

#define OUT_FLOATS  (BATCH * TLEN * DMODEL)       // 2,097,152

// Scratch: projected (pre-scaled) K matrix and per-split partial outputs
__device__ float g_K[BATCH * TLEN * DMODEL];
__device__ float g_part[KSPLIT * OUT_FLOATS];     // 64 MB

// ---------------------------------------------------------------------------
// Packed f32x2 helpers (FFMA2 / FADD2 — PTX only; ptxas never auto-fuses)
// ---------------------------------------------------------------------------
typedef unsigned long long ull;

__device__ __forceinline__ ull pk2(float lo, float hi) {
    ull r; asm("mov.b64 %0, {%1, %2};" : "=l"(r) : "f"(lo), "f"(hi)); return r;
}
__device__ __forceinline__ void upk2(ull v, float& lo, float& hi) {
    asm("mov.b64 {%0, %1}, %2;" : "=f"(lo), "=f"(hi) : "l"(v));
}
__device__ __forceinline__ ull ffma2(ull a, ull b, ull c) {
    ull d; asm("fma.rn.f32x2 %0, %1, %2, %3;" : "=l"(d) : "l"(a), "l"(b), "l"(c)); return d;
}
__device__ __forceinline__ ull fadd2(ull a, ull b) {
    ull d; asm("add.rn.f32x2 %0, %1, %2;" : "=l"(d) : "l"(a), "l"(b)); return d;
}

// ---------------------------------------------------------------------------
// Conv1d(kernel=1) == pointwise linear: gK[b,t,o] = 0.125*(bias[o] + sum_c v[b,t,c]*W[o,c])
// ---------------------------------------------------------------------------
__global__ void conv_kernel(const float* __restrict__ value,
                            const float* __restrict__ w,
                            const float* __restrict__ bias) {
    __shared__ float vsh[16 * DHEAD];
    const int b   = blockIdx.y;
    const int t0  = blockIdx.x * 16;
    const int tid = threadIdx.x;

    const float4* vg = (const float4*)(value + ((size_t)(b * TLEN + t0)) * DHEAD);
    ((float4*)vsh)[tid] = vg[tid];
    __syncthreads();

    for (int o = tid; o < DMODEL; o += 256) {
        ull wreg2[32];
        const ulonglong2* wp = (const ulonglong2*)(w + (size_t)o * DHEAD);
#pragma unroll
        for (int j = 0; j < 16; j++) {
            ulonglong2 ww = wp[j];
            wreg2[2 * j + 0] = ww.x;
            wreg2[2 * j + 1] = ww.y;
        }
        const float bb = bias[o];
        for (int t = 0; t < 16; t++) {
            ull a0 = 0ull, a1 = 0ull;
            const ull* v2 = (const ull*)(vsh + t * DHEAD);
#pragma unroll
            for (int c = 0; c < 32; c += 2) {
                a0 = ffma2(wreg2[c],     v2[c],     a0);
                a1 = ffma2(wreg2[c + 1], v2[c + 1], a1);
            }
            float x0, x1, y0, y1;
            upk2(fadd2(a0, a1), x0, x1);
            const float s = bb + (x0 + x1);
            g_K[((size_t)(b * TLEN + t0 + t)) * DMODEL + o] = s * 0.125f;
        }
    }
}

// ---------------------------------------------------------------------------
// Attention, softmax over HEADS (pointwise in (q,k)).
// 512 threads = 16 warps: warp w -> (h = w>>1, j = w&1). Lane = query index.
// Warp (h,j) handles the d-range [h*64 + j*32, +32):
//   Phase A: partial logits over its 32 d's  -> Sp[j]
//   Softmax: combine halves, softmax over h  -> P in Sp[0]
//   Phase C: accumulate its 32 output d's.
// ---------------------------------------------------------------------------
extern __shared__ float smem[];

__global__ void __launch_bounds__(512, 1)
attn_kernel(const float* __restrict__ query,
            const float* __restrict__ value) {
    float* Ksh = smem;
    float* Vsh = smem + KSH_FLOATS;
    float* Sp  = smem + KSH_FLOATS + VSH_FLOATS;

    const int tid = threadIdx.x;
    const int wid = tid >> 5;
    const int h   = wid >> 1;        // head
    const int j   = wid & 1;         // d-half
    const int qi  = tid & 31;        // lane == query within tile
    const int q0  = blockIdx.x * TQ;
    const int ks  = blockIdx.y;
    const int k0  = ks * KRANGE;
    const int b   = blockIdx.z;

    // q slice for (h, j, qi): 32 floats as 16 ull (LDG.128, no packing movs)
    ull qreg2[16];
    {
        const ulonglong2* qp = (const ulonglong2*)
            (query + ((size_t)(b * TLEN + q0 + qi)) * DMODEL + h * DHEAD + j * 32);
#pragma unroll
        for (int m = 0; m < 8; m++) {
            ulonglong2 t = qp[m];
            qreg2[2 * m + 0] = t.x;
            qreg2[2 * m + 1] = t.y;
        }
    }

    ull o2[16];
#pragma unroll
    for (int m = 0; m < 16; m++) o2[m] = 0ull;

    for (int kt = 0; kt < KRANGE; kt += TK) {
        __syncthreads();  // prev tile fully consumed before overwriting smem

        // ---- load K tile (TK x DMODEL) and V tile (TK x DHEAD), coalesced ----
        {
            const float4* gk4 = (const float4*)(g_K + ((size_t)(b * TLEN + k0 + kt)) * DMODEL);
            float4* k4 = (float4*)Ksh;
#pragma unroll
            for (int r = 0; r < KSH_FLOATS / 4 / 512; r++)
                k4[r * 512 + tid] = gk4[r * 512 + tid];
            const float4* gv4 = (const float4*)(value + ((size_t)(b * TLEN + k0 + kt)) * DHEAD);
            ((float4*)Vsh)[tid] = gv4[tid];
        }
        __syncthreads();

        // ---- Phase A: partial logits over this warp's 32 d's ----
#pragma unroll 2
        for (int ki = 0; ki < TK; ki++) {
            const ulonglong2* kp = (const ulonglong2*)(Ksh + ki * DMODEL + h * DHEAD + j * 32);
            ull a0 = 0ull, a1 = 0ull, a2 = 0ull, a3 = 0ull;
#pragma unroll
            for (int m = 0; m < 8; m += 2) {
                ulonglong2 kA = kp[m];       // warp-broadcast LDS.128
                ulonglong2 kB = kp[m + 1];
                a0 = ffma2(qreg2[2 * m + 0], kA.x, a0);
                a1 = ffma2(qreg2[2 * m + 1], kA.y, a1);
                a2 = ffma2(qreg2[2 * m + 2], kB.x, a2);
                a3 = ffma2(qreg2[2 * m + 3], kB.y, a3);
            }
            float lo, hi;
            upk2(fadd2(fadd2(a0, a1), fadd2(a2, a3)), lo, hi);
            Sp[j * SPHALF + h * (TK * TQ) + ki * TQ + qi] = lo + hi;
        }
        __syncthreads();

        // ---- Softmax over the 8 heads for each (ki, qi); combine d-halves ----
#pragma unroll
        for (int r = 0; r < (TQ * TK) / 512; r++) {
            const int pi  = r * 512 + tid;
            const int kki = pi >> 5;
            const int qqi = pi & 31;       // lane-consecutive -> conflict-free
            float l[NHEADS];
#pragma unroll
            for (int hh = 0; hh < NHEADS; hh++) {
                const int off = hh * (TK * TQ) + kki * TQ + qqi;
                l[hh] = Sp[off] + Sp[SPHALF + off];
            }
            float m = l[0];
#pragma unroll
            for (int hh = 1; hh < NHEADS; hh++) m = fmaxf(m, l[hh]);
            float ssum = 0.f;
#pragma unroll
            for (int hh = 0; hh < NHEADS; hh++) { l[hh] = __expf(l[hh] - m); ssum += l[hh]; }
            const float inv = __fdividef(1.f, ssum);
#pragma unroll
            for (int hh = 0; hh < NHEADS; hh++)
                Sp[hh * (TK * TQ) + kki * TQ + qqi] = l[hh] * inv;
        }
        __syncthreads();

        // ---- Phase C: o2 += P[h][ki][qi] * V[ki][j-half] ----
#pragma unroll 2
        for (int ki = 0; ki < TK; ki++) {
            const float p = Sp[h * (TK * TQ) + ki * TQ + qi];
            const ull pp = pk2(p, p);
            const ulonglong2* vp = (const ulonglong2*)(Vsh + ki * DHEAD + j * 32);
#pragma unroll
            for (int m = 0; m < 8; m++) {
                ulonglong2 vv = vp[m];       // warp-broadcast LDS.128
                o2[2 * m + 0] = ffma2(pp, vv.x, o2[2 * m + 0]);
                o2[2 * m + 1] = ffma2(pp, vv.y, o2[2 * m + 1]);
            }
        }
    }

    // ---- write this split's partial rows (plain stores, no atomics) ----
    float* op = g_part + (size_t)ks * OUT_FLOATS
              + ((size_t)(b * TLEN + q0 + qi)) * DMODEL + h * DHEAD + j * 32;
#pragma unroll
    for (int m = 0; m < 8; m++) {
        float x0, x1, y0, y1;
        upk2(o2[2 * m + 0], x0, x1);
        upk2(o2[2 * m + 1], y0, y1);
        ((float4*)op)[m] = make_float4(x0, x1, y0, y1);
    }
}

// ---------------------------------------------------------------------------
// Final reduce over the KSPLIT partial slabs -> d_out
// ---------------------------------------------------------------------------
__global__ void reduce_kernel(float4* __restrict__ out) {
    const size_t i = (size_t)blockIdx.x * blockDim.x + threadIdx.x;  // float4 index
    const float4* p = (const float4*)g_part;
    const size_t slab = OUT_FLOATS / 4;
    float4 a = p[i];
#pragma unroll
    for (int s = 1; s < KSPLIT; s++) {
        float4 q = p[(size_t)s * slab + i];
        a.x += q.x; a.y += q.y; a.z += q.z; a.w += q.w;
    }
    out[i] = a;
}

// ---------------------------------------------------------------------------
extern "C" void kernel_launch(void* const* d_in, const int* in_sizes, int n_in,
                              void* d_out, int out_size) {
    const float* query = (const float*)d_in[0];   // [2,2048,512]
    const float* value = (const float*)d_in[1];   // [2,2048,64]
    const float* convw = (const float*)d_in[2];   // [512,64,1]
    const float* convb = (const float*)d_in[3];   // [512]
    float* out = (float*)d_out;                   // [2,2048,512]

    cudaFuncSetAttribute(attn_kernel, cudaFuncAttributeMaxDynamicSharedMemorySize, SMEM_BYTES);

    conv_kernel<<<dim3(TLEN / 16, BATCH), 256>>>(value, convw, convb);
    attn_kernel<<<dim3(TLEN / TQ, KSPLIT, BATCH), 512, SMEM_BYTES>>>(query, value);
    reduce_kernel<<<(OUT_FLOATS / 4) / 256, 256>>>((float4*)out);
}

// round 12
// speedup vs baseline: 1.4963x; 1.4963x over previous
#include <cuda_runtime.h>
#include <cuda_bf16.h>
#include <cstddef>

// Problem constants
#define BATCH   2
#define TLEN    2048       // Tq == Tv
#define DMODEL  512
#define NHEADS  8
#define DHEAD   64

// Tiling
#define TQ      32         // queries per block
#define TK      64         // keys per tile
#define KSPLIT  8          // k-range splits per (b, q-tile)
#define KRANGE  (TLEN / KSPLIT)   // 256 keys per block

// Shared layout (floats): Ksh[TK*DMODEL] | Vsh[TK*DHEAD] | Psh[NHEADS*TK*TQ]
#define KSH_FLOATS  (TK * DMODEL)                 // 32768
#define VSH_FLOATS  (TK * DHEAD)                  // 4096
#define PSH_FLOATS  (NHEADS * TK * TQ)            // 16384
#define SMEM_FLOATS (KSH_FLOATS + VSH_FLOATS + PSH_FLOATS)
#define SMEM_BYTES  (SMEM_FLOATS * 4)             // 212992

#define OUT_FLOATS  (BATCH * TLEN * DMODEL)       // 2,097,152

// Scratch: projected (pre-scaled) K matrix and per-split partial outputs
__device__ float g_K[BATCH * TLEN * DMODEL];
__device__ float g_part[KSPLIT * OUT_FLOATS];     // 64 MB

// ---------------------------------------------------------------------------
// Packed f32x2 helpers (FFMA2 / FADD2 — PTX only; ptxas never auto-fuses)
// ---------------------------------------------------------------------------
typedef unsigned long long ull;

__device__ __forceinline__ ull pk2(float lo, float hi) {
    ull r; asm("mov.b64 %0, {%1, %2};" : "=l"(r) : "f"(lo), "f"(hi)); return r;
}
__device__ __forceinline__ void upk2(ull v, float& lo, float& hi) {
    asm("mov.b64 {%0, %1}, %2;" : "=f"(lo), "=f"(hi) : "l"(v));
}
__device__ __forceinline__ ull ffma2(ull a, ull b, ull c) {
    ull d; asm("fma.rn.f32x2 %0, %1, %2, %3;" : "=l"(d) : "l"(a), "l"(b), "l"(c)); return d;
}
__device__ __forceinline__ ull fadd2(ull a, ull b) {
    ull d; asm("add.rn.f32x2 %0, %1, %2;" : "=l"(d) : "l"(a), "l"(b)); return d;
}

// ---------------------------------------------------------------------------
// Conv1d(kernel=1) == pointwise linear: gK[b,t,o] = 0.125*(bias[o] + sum_c v[b,t,c]*W[o,c])
// Grid (TLEN/4, BATCH) x 256 threads: 4 t-rows per block, 2 outputs per thread.
// ---------------------------------------------------------------------------
__global__ void conv_kernel(const float* __restrict__ value,
                            const float* __restrict__ w,
                            const float* __restrict__ bias) {
    __shared__ float vsh[4 * DHEAD];
    const int b   = blockIdx.y;
    const int t0  = blockIdx.x * 4;
    const int tid = threadIdx.x;

    if (tid < 64) {
        const float4* vg = (const float4*)(value + ((size_t)(b * TLEN + t0)) * DHEAD);
        ((float4*)vsh)[tid] = vg[tid];
    }
    __syncthreads();

    for (int o = tid; o < DMODEL; o += 256) {
        ull wreg2[32];
        const ulonglong2* wp = (const ulonglong2*)(w + (size_t)o * DHEAD);
#pragma unroll
        for (int j = 0; j < 16; j++) {
            ulonglong2 ww = wp[j];
            wreg2[2 * j + 0] = ww.x;
            wreg2[2 * j + 1] = ww.y;
        }
        const float bb = bias[o];
#pragma unroll
        for (int t = 0; t < 4; t++) {
            ull a0 = 0ull, a1 = 0ull;
            const ull* v2 = (const ull*)(vsh + t * DHEAD);
#pragma unroll
            for (int c = 0; c < 32; c += 2) {
                a0 = ffma2(wreg2[c],     v2[c],     a0);
                a1 = ffma2(wreg2[c + 1], v2[c + 1], a1);
            }
            float x0, x1;
            upk2(fadd2(a0, a1), x0, x1);
            const float s = bb + (x0 + x1);
            g_K[((size_t)(b * TLEN + t0 + t)) * DMODEL + o] = s * 0.125f;
        }
    }
}

// ---------------------------------------------------------------------------
// Attention with softmax over HEADS (pointwise in (q,k)):
// Block: 256 threads, warp w == head h, lane == qi. Writes a partial-output
// slab for its k-split (no atomics).
// ---------------------------------------------------------------------------
extern __shared__ float smem[];

__global__ void __launch_bounds__(256, 1)
attn_kernel(const float* __restrict__ query,
            const float* __restrict__ value) {
    float* Ksh = smem;
    float* Vsh = smem + KSH_FLOATS;
    float* Psh = smem + KSH_FLOATS + VSH_FLOATS;

    const int tid = threadIdx.x;
    const int h   = tid >> 5;   // warp index == head
    const int qi  = tid & 31;   // lane == query within tile
    const int q0  = blockIdx.x * TQ;
    const int ks  = blockIdx.y;
    const int k0  = ks * KRANGE;
    const int b   = blockIdx.z;

    // q row for (h, qi): 64 floats as 32 packed f32x2 (LDG.128, no packing movs)
    ull qreg2[32];
    {
        const ulonglong2* qp = (const ulonglong2*)
            (query + ((size_t)(b * TLEN + q0 + qi)) * DMODEL + h * DHEAD);
#pragma unroll
        for (int m = 0; m < 16; m++) {
            ulonglong2 t = qp[m];
            qreg2[2 * m + 0] = t.x;
            qreg2[2 * m + 1] = t.y;
        }
    }

    ull o2[32];
#pragma unroll
    for (int d = 0; d < 32; d++) o2[d] = 0ull;

    for (int kt = 0; kt < KRANGE; kt += TK) {
        __syncthreads();  // previous tile's phase C done before overwriting tiles

        // ---- load K tile (TK x DMODEL) and V tile (TK x DHEAD), coalesced ----
        {
            const float4* gk4 = (const float4*)(g_K + ((size_t)(b * TLEN + k0 + kt)) * DMODEL);
            float4* k4 = (float4*)Ksh;
#pragma unroll
            for (int r = 0; r < KSH_FLOATS / 4 / 256; r++)
                k4[r * 256 + tid] = gk4[r * 256 + tid];
            const float4* gv4 = (const float4*)(value + ((size_t)(b * TLEN + k0 + kt)) * DHEAD);
            float4* v4 = (float4*)Vsh;
#pragma unroll
            for (int r = 0; r < VSH_FLOATS / 4 / 256; r++)
                v4[r * 256 + tid] = gv4[r * 256 + tid];
        }
        __syncthreads();

        // ---- Phase A: logits S[h][ki][qi] = qreg . Ksh[ki][h*64:...] (f32x2) ----
        // 64-float dot: kp has 16 ulonglong2 entries (4 floats each).
#pragma unroll 4
        for (int ki = 0; ki < TK; ki++) {
            const ulonglong2* kp = (const ulonglong2*)(Ksh + ki * DMODEL + h * DHEAD);  // broadcast
            ull a0 = 0ull, a1 = 0ull, a2 = 0ull, a3 = 0ull;
#pragma unroll
            for (int m = 0; m < 16; m += 2) {
                ulonglong2 kA = kp[m];       // floats [4m, 4m+4)
                ulonglong2 kB = kp[m + 1];   // floats [4m+4, 4m+8)
                a0 = ffma2(qreg2[2 * m + 0], kA.x, a0);
                a1 = ffma2(qreg2[2 * m + 1], kA.y, a1);
                a2 = ffma2(qreg2[2 * m + 2], kB.x, a2);
                a3 = ffma2(qreg2[2 * m + 3], kB.y, a3);
            }
            float lo, hi;
            upk2(fadd2(fadd2(a0, a1), fadd2(a2, a3)), lo, hi);
            Psh[h * (TK * TQ) + ki * TQ + qi] = lo + hi;
        }
        __syncthreads();

        // ---- Phase B: softmax over the 8 heads for each (ki, qi) pair ----
#pragma unroll
        for (int r = 0; r < (TQ * TK) / 256; r++) {
            const int pi  = r * 256 + tid;
            const int kki = pi >> 5;       // ki
            const int qqi = pi & 31;       // qi (lane-consecutive -> conflict-free)
            float l[NHEADS];
#pragma unroll
            for (int hh = 0; hh < NHEADS; hh++)
                l[hh] = Psh[hh * (TK * TQ) + kki * TQ + qqi];
            float m = l[0];
#pragma unroll
            for (int hh = 1; hh < NHEADS; hh++) m = fmaxf(m, l[hh]);
            float ssum = 0.f;
#pragma unroll
            for (int hh = 0; hh < NHEADS; hh++) { l[hh] = __expf(l[hh] - m); ssum += l[hh]; }
            const float inv = __fdividef(1.f, ssum);
#pragma unroll
            for (int hh = 0; hh < NHEADS; hh++)
                Psh[hh * (TK * TQ) + kki * TQ + qqi] = l[hh] * inv;
        }
        __syncthreads();

        // ---- Phase C: o2[.] += P[h][ki][qi] * Vsh[ki][.] (f32x2, full 64 d's) ----
#pragma unroll 4
        for (int ki = 0; ki < TK; ki++) {
            const float p = Psh[h * (TK * TQ) + ki * TQ + qi];
            const ull pp = pk2(p, p);
            const ulonglong2* vp = (const ulonglong2*)(Vsh + ki * DHEAD);  // broadcast
#pragma unroll
            for (int m = 0; m < 16; m++) {
                ulonglong2 vv = vp[m];       // LDS.128, floats [4m, 4m+4)
                o2[2 * m + 0] = ffma2(pp, vv.x, o2[2 * m + 0]);
                o2[2 * m + 1] = ffma2(pp, vv.y, o2[2 * m + 1]);
            }
        }
    }

    // ---- write this split's partial rows (plain stores, no atomics) ----
    float* op = g_part + (size_t)ks * OUT_FLOATS
              + ((size_t)(b * TLEN + q0 + qi)) * DMODEL + h * DHEAD;
#pragma unroll
    for (int m = 0; m < 16; m++) {
        float x0, x1, y0, y1;
        upk2(o2[2 * m + 0], x0, x1);
        upk2(o2[2 * m + 1], y0, y1);
        ((float4*)op)[m] = make_float4(x0, x1, y0, y1);
    }
}

// ---------------------------------------------------------------------------
// Final reduce over the KSPLIT partial slabs -> d_out
// ---------------------------------------------------------------------------
__global__ void reduce_kernel(float4* __restrict__ out) {
    const size_t i = (size_t)blockIdx.x * blockDim.x + threadIdx.x;  // float4 index
    const float4* p = (const float4*)g_part;
    const size_t slab = OUT_FLOATS / 4;
    float4 a = p[i];
#pragma unroll
    for (int s = 1; s < KSPLIT; s++) {
        float4 q = p[(size_t)s * slab + i];
        a.x += q.x; a.y += q.y; a.z += q.z; a.w += q.w;
    }
    out[i] = a;
}

// ---------------------------------------------------------------------------
extern "C" void kernel_launch(void* const* d_in, const int* in_sizes, int n_in,
                              void* d_out, int out_size) {
    const float* query = (const float*)d_in[0];   // [2,2048,512]
    const float* value = (const float*)d_in[1];   // [2,2048,64]
    const float* convw = (const float*)d_in[2];   // [512,64,1]
    const float* convb = (const float*)d_in[3];   // [512]
    float* out = (float*)d_out;                   // [2,2048,512]

    cudaFuncSetAttribute(attn_kernel, cudaFuncAttributeMaxDynamicSharedMemorySize, SMEM_BYTES);

    conv_kernel<<<dim3(TLEN / 4, BATCH), 256>>>(value, convw, convb);
    attn_kernel<<<dim3(TLEN / TQ, KSPLIT, BATCH), 256, SMEM_BYTES>>>(query, value);
    reduce_kernel<<<(OUT_FLOATS / 4) / 256, 256>>>((float4*)out);
}